// round 9
// baseline (speedup 1.0000x reference)
#include <cuda_runtime.h>
#include <cuda_bf16.h>
#include <cstdint>

// Problem constants (B=32, C=1 heat, H=W=256, K=500)
#define NB     32
#define WID    256
#define HW     65536
#define KTOP   500
#define NIMG   64          // 32 pred images (NMS'd) + 32 gt images (raw)
#define CAND_MAX 8192      // max stored NMS candidates per pred image (~7.3k expected)
#define SURV   1024        // survivors after value-bin prune (E~516, 20-sigma margin)
#define BINS   4096        // value-based bins: bin = clamp((int)(v*4096), 0, 4095)

#define RCHUNK 8                 // rows per k_nms block
#define NCHUNK (WID / RCHUNK)    // 32
#define STAGE_MAX 512            // per-block candidate staging (E~228, +20 sigma)

#define GSL   8                  // gt slices per image
#define SLPX  (HW / GSL)         // 8192 pixels per slice

// Scratch (static device globals — zero-initialized; every consumer resets what
// it consumed so graph replays see the same initial state)
__device__ unsigned long long g_cand[NB][CAND_MAX];     // 2 MB (pred NMS survivors)
__device__ int      g_cnt[NB];
__device__ int      g_hist[NB][BINS];                   // 512 KB (gt histograms)
__device__ unsigned long long g_gtkeys[NB][SURV];       // 256 KB (gt survivors)
__device__ int      g_gtcnt[NB];
__device__ float    g_xs[NIMG][KTOP];
__device__ float    g_ys[NIMG][KTOP];
__device__ double   g_sum;
__device__ int      g_tot;
__device__ unsigned g_ticket;

// per-coordinate assembly tables (see reference _assemble)
__constant__ int   c_whA[10] = {-1,-1, 0, 1, 2, 3, 4, 5, 6, 7};   // m==1: wh channel
__constant__ int   c_whB[10] = {-1,-1,-1, 9, 8,-1,-1, 9, 8,-1};   // m==0: wh channel
__constant__ float c_sgn[10] = {0,0,0,-0.5f,0.5f,0,0,0.5f,-0.5f,0};

__device__ __forceinline__ int val_bin(float v) {
    int b = (int)(v * 4096.0f);
    if (b < 0) b = 0;
    if (b > BINS - 1) b = BINS - 1;
    return b;   // monotone non-decreasing in v
}

__device__ __forceinline__ unsigned long long uomin(unsigned long long a, unsigned long long b) { return a < b ? a : b; }
__device__ __forceinline__ unsigned long long uomax(unsigned long long a, unsigned long long b) { return a > b ? a : b; }

// ---------------------------------------------------------------------------
// suffix-scan over 4096 smem bins -> smallest bin index with suffix-count >= K
// (all 1024 threads must call; contains barriers)
__device__ __forceinline__ int compute_bstar(const int* hist, int* psum,
                                             int* wsuf, int* s_bstar, int tid) {
    int lane = tid & 31, warp = tid >> 5;
    int v = hist[4*tid] + hist[4*tid+1] + hist[4*tid+2] + hist[4*tid+3];
    #pragma unroll
    for (int off = 1; off < 32; off <<= 1) {
        int t2 = __shfl_down_sync(0xffffffffu, v, off);
        if (lane + off < 32) v += t2;
    }
    if (lane == 0) wsuf[warp] = v;
    __syncthreads();
    if (warp == 0) {
        int t = wsuf[lane];
        #pragma unroll
        for (int off = 1; off < 32; off <<= 1) {
            int t2 = __shfl_down_sync(0xffffffffu, t, off);
            if (lane + off < 32) t += t2;
        }
        wsuf[lane] = t;
    }
    __syncthreads();
    int suffix = v + ((warp < 31) ? wsuf[warp + 1] : 0);
    psum[tid] = suffix;
    __syncthreads();
    int above = (tid < 1023) ? psum[tid + 1] : 0;
    if (psum[tid] >= KTOP && above < KTOP) {
        int c = above;
        int bstar = 4 * tid;
        for (int b = 4 * tid + 3; b >= 4 * tid; --b) {
            c += hist[b];
            if (c >= KTOP) { bstar = b; break; }
        }
        *s_bstar = bstar;
    }
    __syncthreads();
    return *s_bstar;
}

// bitonic sort ascending over 1024 smem keys; shuffle stages for j<=16
// (all 1024 threads must call; contains barriers)
__device__ __forceinline__ void bitonic1024(unsigned long long* keys, int tid) {
    {
        unsigned long long kv = keys[tid];
        #pragma unroll
        for (unsigned kk = 2; kk <= 32; kk <<= 1) {
            bool up = ((tid & kk) == 0);
            #pragma unroll
            for (unsigned j = kk >> 1; j >= 1; j >>= 1) {
                unsigned long long pv = __shfl_xor_sync(0xffffffffu, kv, j);
                bool keepmin = (((tid & j) == 0) == up);
                kv = keepmin ? uomin(kv, pv) : uomax(kv, pv);
            }
        }
        keys[tid] = kv;
    }
    __syncthreads();
    for (unsigned kk = 64; kk <= SURV; kk <<= 1) {
        bool up = ((tid & kk) == 0);
        for (unsigned j = kk >> 1; j >= 32; j >>= 1) {
            unsigned ixj = tid ^ j;
            if (ixj > tid) {
                unsigned long long a = keys[tid], b = keys[ixj];
                if ((a > b) == up) { keys[tid] = b; keys[ixj] = a; }
            }
            __syncthreads();
        }
        unsigned long long kv = keys[tid];
        #pragma unroll
        for (unsigned j = 16; j >= 1; j >>= 1) {
            unsigned long long pv = __shfl_xor_sync(0xffffffffu, kv, j);
            bool keepmin = (((tid & j) == 0) == up);
            kv = keepmin ? uomin(kv, pv) : uomax(kv, pv);
        }
        keys[tid] = kv;
        __syncthreads();
    }
}

// ---------------------------------------------------------------------------
// 3x3 NMS on PRED heatmaps only (reference NMS-es pred_hm, not gt_hm).
// One block per (image, 8-row chunk). Pixel survives iff v>0 and v >= max of
// its 3x3 window (window includes v => exactly hmax==heat).
__global__ void __launch_bounds__(WID) k_nms(const float* __restrict__ pred_hm) {
    __shared__ float rows[RCHUNK + 2][WID];              // 10 KB
    __shared__ unsigned long long stage[STAGE_MAX];      // 4 KB
    __shared__ int s_cnt, s_base;

    int img   = blockIdx.x >> 5;            // / NCHUNK
    int chunk = blockIdx.x & (NCHUNK - 1);
    int y0 = chunk * RCHUNK;
    const float* hm = pred_hm + (size_t)img * HW;
    int x = threadIdx.x;

    #pragma unroll
    for (int r = 0; r < RCHUNK + 2; r++) {
        int y = y0 - 1 + r;
        rows[r][x] = (y >= 0 && y < WID) ? __ldg(&hm[y * WID + x]) : -1.0f;
    }
    if (x == 0) s_cnt = 0;
    __syncthreads();

    auto hmax3 = [&](int r) {
        float m = rows[r][x];
        if (x > 0)       m = fmaxf(m, rows[r][x - 1]);
        if (x < WID - 1) m = fmaxf(m, rows[r][x + 1]);
        return m;
    };
    float hprev = hmax3(0);
    float hcur  = hmax3(1);
    int lane = x & 31;

    #pragma unroll
    for (int r = 1; r <= RCHUNK; r++) {
        float hnext = hmax3(r + 1);
        float v = rows[r][x];
        bool ok = (v > 0.0f) && (v >= hprev) && (v >= hcur) && (v >= hnext);
        unsigned ballot = __ballot_sync(0xffffffffu, ok);
        if (ok) {
            int leader = __ffs(ballot) - 1;
            int base = 0;
            if (lane == leader) base = atomicAdd(&s_cnt, __popc(ballot));
            base = __shfl_sync(ballot, base, leader);
            int slot = base + __popc(ballot & ((1u << lane) - 1u));
            if (slot < STAGE_MAX) {
                unsigned fb = __float_as_uint(v);   // v > 0 => monotone bits
                stage[slot] = ((unsigned long long)(~fb) << 32)
                            | (unsigned)((y0 - 1 + r) * WID + x);
            }
        }
        hprev = hcur; hcur = hnext;
    }
    __syncthreads();

    int cnt = s_cnt; if (cnt > STAGE_MAX) cnt = STAGE_MAX;
    if (x == 0) s_base = atomicAdd(&g_cnt[img], cnt);
    __syncthreads();
    int base = s_base;
    for (int i = x; i < cnt; i += WID) {
        int slot = base + i;
        if (slot < CAND_MAX) g_cand[img][slot] = stage[i];
    }
}

// ---------------------------------------------------------------------------
// PRED exact ordered top-500 (one CTA per image; operates on NMS survivors).
__global__ void __launch_bounds__(1024) k_select_pred() {
    __shared__ int hist[BINS];
    __shared__ unsigned long long keys[SURV];
    __shared__ int psum[1024];
    __shared__ int wsuf[32];
    __shared__ int s_bstar, s_nsurv;

    int img = blockIdx.x;
    int tid = threadIdx.x;
    int lane = tid & 31;
    int n = g_cnt[img]; if (n > CAND_MAX) n = CAND_MAX;

    for (int i = tid; i < BINS; i += 1024) hist[i] = 0;
    if (tid == 0) { s_bstar = 0; s_nsurv = 0; }
    __syncthreads();

    for (int i = tid; i < n; i += 1024) {
        float v = __uint_as_float(~(unsigned)(g_cand[img][i] >> 32));
        atomicAdd(&hist[val_bin(v)], 1);
    }
    __syncthreads();

    int bstar = compute_bstar(hist, psum, wsuf, &s_bstar, tid);

    int n_pad = (n + 1023) & ~1023;
    for (int i = tid; i < n_pad; i += 1024) {
        unsigned long long key = 0; bool pass = false;
        if (i < n) {
            key = g_cand[img][i];
            float vv = __uint_as_float(~(unsigned)(key >> 32));
            pass = (val_bin(vv) >= bstar);
        }
        unsigned ballot = __ballot_sync(0xffffffffu, pass);
        if (pass) {
            int leader = __ffs(ballot) - 1;
            int base = 0;
            if (lane == leader) base = atomicAdd(&s_nsurv, __popc(ballot));
            base = __shfl_sync(ballot, base, leader);
            int slot = base + __popc(ballot & ((1u << lane) - 1u));
            if (slot < SURV) keys[slot] = key;
        }
    }
    __syncthreads();
    int ns = s_nsurv; if (ns > SURV) ns = SURV;
    if (tid >= ns) keys[tid] = 0xFFFFFFFFFFFFFFFFULL;
    __syncthreads();

    bitonic1024(keys, tid);

    if (tid < KTOP) {
        unsigned p = (unsigned)(keys[tid] & 0xFFFFFFFFULL);
        g_xs[img][tid] = (float)(p & (WID - 1));
        g_ys[img][tid] = (float)(p >> 8);
    }
    if (tid == 0) g_cnt[img] = 0;   // reset for next graph replay
}

// ---------------------------------------------------------------------------
// GT top-500, phase 1: per-slice histogram (8 CTAs per image).
__global__ void __launch_bounds__(1024) k_gt_hist(const float* __restrict__ gt_hm) {
    __shared__ int hist[BINS];
    int blk = blockIdx.x;
    int img = blk >> 3, sl = blk & (GSL - 1);
    const float4* hm4 = reinterpret_cast<const float4*>(
        gt_hm + (size_t)img * HW + sl * SLPX);
    int tid = threadIdx.x;
    for (int i = tid; i < BINS; i += 1024) hist[i] = 0;
    __syncthreads();
    #pragma unroll
    for (int i = tid; i < SLPX / 4; i += 1024) {
        float4 v = __ldg(&hm4[i]);
        atomicAdd(&hist[val_bin(v.x)], 1);
        atomicAdd(&hist[val_bin(v.y)], 1);
        atomicAdd(&hist[val_bin(v.z)], 1);
        atomicAdd(&hist[val_bin(v.w)], 1);
    }
    __syncthreads();
    for (int i = tid; i < BINS; i += 1024) {
        int h = hist[i];
        if (h) atomicAdd(&g_hist[img][i], h);
    }
}

// GT phase 2: per-slice survivor collection (8 CTAs per image; each CTA
// recomputes bstar from the merged global histogram — cheap L2 reads).
__global__ void __launch_bounds__(1024) k_gt_collect(const float* __restrict__ gt_hm) {
    __shared__ int hist[BINS];
    __shared__ int psum[1024];
    __shared__ int wsuf[32];
    __shared__ int s_bstar;
    int blk = blockIdx.x;
    int img = blk >> 3, sl = blk & (GSL - 1);
    int tid = threadIdx.x;
    int lane = tid & 31;
    for (int i = tid; i < BINS; i += 1024) hist[i] = g_hist[img][i];
    if (tid == 0) s_bstar = 0;
    __syncthreads();
    int bstar = compute_bstar(hist, psum, wsuf, &s_bstar, tid);

    const float4* hm4 = reinterpret_cast<const float4*>(
        gt_hm + (size_t)img * HW + sl * SLPX);
    int pix0 = sl * SLPX;
    #pragma unroll
    for (int i = tid; i < SLPX / 4; i += 1024) {
        float4 v4 = __ldg(&hm4[i]);
        float vv[4] = {v4.x, v4.y, v4.z, v4.w};
        #pragma unroll
        for (int comp = 0; comp < 4; comp++) {
            bool pass = (val_bin(vv[comp]) >= bstar);
            unsigned ballot = __ballot_sync(0xffffffffu, pass);
            if (pass) {
                int leader = __ffs(ballot) - 1;
                int base = 0;
                if (lane == leader) base = atomicAdd(&g_gtcnt[img], __popc(ballot));
                base = __shfl_sync(ballot, base, leader);
                int slot = base + __popc(ballot & ((1u << lane) - 1u));
                if (slot < SURV) {
                    unsigned fb = __float_as_uint(vv[comp]);
                    g_gtkeys[img][slot] = ((unsigned long long)(~fb) << 32)
                                        | (unsigned)(pix0 + 4 * i + comp);
                }
            }
        }
    }
}

// GT phase 3: sort survivors, emit ranked coords, reset scratch.
__global__ void __launch_bounds__(1024) k_gt_sort() {
    __shared__ unsigned long long keys[SURV];
    int img = blockIdx.x;
    int tid = threadIdx.x;
    int ns = g_gtcnt[img]; if (ns > SURV) ns = SURV;
    keys[tid] = (tid < ns) ? g_gtkeys[img][tid] : 0xFFFFFFFFFFFFFFFFULL;
    __syncthreads();
    bitonic1024(keys, tid);
    if (tid < KTOP) {
        unsigned p = (unsigned)(keys[tid] & 0xFFFFFFFFULL);
        g_xs[NB + img][tid] = (float)(p & (WID - 1));
        g_ys[NB + img][tid] = (float)(p >> 8);
    }
    // reset consumed scratch for next graph replay
    if (tid == 0) g_gtcnt[img] = 0;
    for (int i = tid; i < BINS; i += 1024) g_hist[img][i] = 0;
}

// ---------------------------------------------------------------------------
// Loss: one thread per (item, coordinate, side) — 320K threads.
// side 0 computes the pred coordinate (scattered gathers), side 1 the gt
// coordinate (coalesced); paired via shfl_xor(1). m is exactly 0/1 in the
// reference so branching is bit-exact with the blend.
#define LOSS_TPB 1024
#define LOSS_N2  (NB * KTOP * 20)
__global__ void __launch_bounds__(LOSS_TPB)
k_loss(const float* __restrict__ pred_wh, const float* __restrict__ pred_reg,
       const float* __restrict__ pred_cls,
       const float* __restrict__ gt_wh, const float* __restrict__ gt_reg,
       const float* __restrict__ gt_cls,
       const int* __restrict__ gt_ind, const int* __restrict__ gt_mask,
       float* __restrict__ out) {
    int gidx = blockIdx.x * LOSS_TPB + threadIdx.x;
    float val = 0.f;
    int mask = 0;
    bool gtside = gidx & 1;
    if (gidx < LOSS_N2) {
        int t = gidx / 20;
        int rem = gidx - t * 20;
        int c = rem >> 1;
        mask = __ldg(&gt_mask[t]);
        if (mask) {
            int b = t / KTOP, k = t - b * KTOP;
            bool odd = c & 1;
            int iA = c_whA[c], iB = c_whB[c];
            float sg = c_sgn[c];
            if (gtside) {
                float base = odd ? (g_ys[NB + b][k] + __ldg(&gt_reg[2 * t + 1]))
                                 : (g_xs[NB + b][k] + __ldg(&gt_reg[2 * t]));
                bool gm = __ldg(&gt_cls[t]) > 0.8f;
                val = base;
                if (gm) { if (iA >= 0) val += __ldg(&gt_wh[10 * t + iA]); }
                else    { if (iB >= 0) val += sg * __ldg(&gt_wh[10 * t + iB]); }
            } else {
                int ind = __ldg(&gt_ind[t]);
                float base = odd ? (g_ys[b][k] + __ldg(&pred_reg[(size_t)(b * 2 + 1) * HW + ind]))
                                 : (g_xs[b][k] + __ldg(&pred_reg[(size_t)(b * 2) * HW + ind]));
                bool m = __ldg(&pred_cls[(size_t)b * HW + ind]) > 0.8f;
                val = base;
                if (m) { if (iA >= 0) val += __ldg(&pred_wh[((size_t)b * 10 + iA) * HW + ind]); }
                else   { if (iB >= 0) val += sg * __ldg(&pred_wh[((size_t)b * 10 + iB) * HW + ind]); }
            }
        }
    }
    float other = __shfl_xor_sync(0xffffffffu, val, 1);
    float lsum = 0.f;
    int lcnt = 0;
    if (gidx < LOSS_N2 && !gtside && mask) {
        float d = fabsf(val - other);
        lsum = (d < 1.f) ? 0.5f * d * d : (d - 0.5f);
        lcnt = 1;
    }
    // block reduce (32 warps)
    #pragma unroll
    for (int off = 16; off > 0; off >>= 1) {
        lsum += __shfl_down_sync(0xffffffffu, lsum, off);
        lcnt += __shfl_down_sync(0xffffffffu, lcnt, off);
    }
    __shared__ float wsum[LOSS_TPB / 32];
    __shared__ int   wcnt[LOSS_TPB / 32];
    int warp = threadIdx.x >> 5, lane = threadIdx.x & 31;
    if (lane == 0) { wsum[warp] = lsum; wcnt[warp] = lcnt; }
    __syncthreads();
    if (warp == 0) {
        float s = (lane < LOSS_TPB / 32) ? wsum[lane] : 0.f;
        int   cc = (lane < LOSS_TPB / 32) ? wcnt[lane] : 0;
        #pragma unroll
        for (int off = 16; off > 0; off >>= 1) {
            s  += __shfl_down_sync(0xffffffffu, s, off);
            cc += __shfl_down_sync(0xffffffffu, cc, off);
        }
        if (lane == 0) {
            atomicAdd(&g_sum, (double)s);
            atomicAdd(&g_tot, cc);
            __threadfence();
            unsigned ticket = atomicAdd(&g_ticket, 1u);
            if (ticket == gridDim.x - 1) {   // last block: finalize + reset
                double fs = g_sum;
                int tot = g_tot;
                float loss = 0.f;
                if (tot > 0) loss = (float)(fs / (double)(tot < 1 ? 1 : tot));
                out[0] = loss;
                g_sum = 0.0; g_tot = 0; g_ticket = 0u;
            }
        }
    }
}

// ---------------------------------------------------------------------------
extern "C" void kernel_launch(void* const* d_in, const int* in_sizes, int n_in,
                              void* d_out, int out_size) {
    const float* pred_hm  = (const float*)d_in[0];
    const float* pred_wh  = (const float*)d_in[1];
    const float* pred_reg = (const float*)d_in[2];
    const float* pred_cls = (const float*)d_in[3];
    const float* gt_hm    = (const float*)d_in[4];
    const float* gt_wh    = (const float*)d_in[5];
    const float* gt_reg   = (const float*)d_in[6];
    const float* gt_cls   = (const float*)d_in[7];
    const int*   gt_ind   = (const int*)d_in[8];
    const int*   gt_mask  = (const int*)d_in[9];
    float* out = (float*)d_out;

    // side stream for the gt top-k branch (independent of pred NMS path).
    // Created once on the first (non-captured) correctness call; fork/join via
    // events so graph capture records two parallel branches.
    static cudaStream_t s2 = nullptr;
    static cudaEvent_t evFork = nullptr, evJoin = nullptr;
    if (s2 == nullptr) {
        cudaStreamCreateWithFlags(&s2, cudaStreamNonBlocking);
        cudaEventCreateWithFlags(&evFork, cudaEventDisableTiming);
        cudaEventCreateWithFlags(&evJoin, cudaEventDisableTiming);
    }

    cudaEventRecord(evFork, 0);
    cudaStreamWaitEvent(s2, evFork, 0);
    k_gt_hist<<<NB * GSL, 1024, 0, s2>>>(gt_hm);      // gt branch
    k_gt_collect<<<NB * GSL, 1024, 0, s2>>>(gt_hm);
    k_gt_sort<<<NB, 1024, 0, s2>>>();
    cudaEventRecord(evJoin, s2);

    k_nms<<<NB * NCHUNK, WID>>>(pred_hm);             // pred branch
    k_select_pred<<<NB, 1024>>>();

    cudaStreamWaitEvent(0, evJoin, 0);
    k_loss<<<(LOSS_N2 + LOSS_TPB - 1) / LOSS_TPB, LOSS_TPB>>>(
        pred_wh, pred_reg, pred_cls, gt_wh, gt_reg, gt_cls, gt_ind, gt_mask, out);
}

// round 10
// speedup vs baseline: 1.0343x; 1.0343x over previous
#include <cuda_runtime.h>
#include <cuda_bf16.h>
#include <cstdint>

// Problem constants (B=32, C=1 heat, H=W=256, K=500)
#define NB     32
#define WID    256
#define HW     65536
#define KTOP   500
#define NIMG   64
#define CAND_MAX 8192      // per pred image (~7.3k expected)
#define SURV   1024        // sort width (survivors E~516)
#define BINS   4096        // value bins: clamp((int)(v*4096), 0, 4095)

#define RCHUNK 16                // rows per k_nms block
#define NCHUNK (WID / RCHUNK)    // 16
#define STAGE_ROWS (RCHUNK + 2)  // 18
#define STAGE_MAX 1024           // per-block staging (E~455, +28 sigma)

#define PRE_THRESH 0.98f
#define PRE_MAX    1536          // gt prefilter buffer (E~1311, +6 sigma)
#define SAFE_BIN   4015          // bin 4015 starts at 4015/4096 > 0.98

// Scratch (static device globals — zero-init; consumers reset what they use)
__device__ unsigned long long g_cand[NB][CAND_MAX];     // pred NMS survivors
__device__ int      g_cnt[NB];
__device__ float    g_xs[NIMG][KTOP];
__device__ float    g_ys[NIMG][KTOP];
__device__ double   g_sum;
__device__ int      g_tot;
__device__ unsigned g_ticket;

// per-coordinate assembly tables (see reference _assemble)
__constant__ int   c_whA[10] = {-1,-1, 0, 1, 2, 3, 4, 5, 6, 7};   // m==1
__constant__ int   c_whB[10] = {-1,-1,-1, 9, 8,-1,-1, 9, 8,-1};   // m==0
__constant__ float c_sgn[10] = {0,0,0,-0.5f,0.5f,0,0,0.5f,-0.5f,0};

__device__ __forceinline__ int val_bin(float v) {
    int b = (int)(v * 4096.0f);
    if (b < 0) b = 0;
    if (b > BINS - 1) b = BINS - 1;
    return b;   // monotone non-decreasing in v
}
__device__ __forceinline__ unsigned long long uomin(unsigned long long a, unsigned long long b) { return a < b ? a : b; }
__device__ __forceinline__ unsigned long long uomax(unsigned long long a, unsigned long long b) { return a > b ? a : b; }
__device__ __forceinline__ float max3f(float a, float b, float c) { return fmaxf(a, fmaxf(b, c)); }

// suffix-scan over 4096 smem bins (no psum array): smallest bin with
// suffix-count >= KTOP. All 1024 threads must call (barriers inside).
__device__ __forceinline__ int compute_bstar(const int* hist, int* wsuf,
                                             int* s_bstar, int tid) {
    int lane = tid & 31, warp = tid >> 5;
    int gv = hist[4*tid] + hist[4*tid+1] + hist[4*tid+2] + hist[4*tid+3];
    int v = gv;
    #pragma unroll
    for (int off = 1; off < 32; off <<= 1) {
        int t2 = __shfl_down_sync(0xffffffffu, v, off);
        if (lane + off < 32) v += t2;
    }
    if (lane == 0) wsuf[warp] = v;
    __syncthreads();
    if (warp == 0) {
        int t = wsuf[lane];
        #pragma unroll
        for (int off = 1; off < 32; off <<= 1) {
            int t2 = __shfl_down_sync(0xffffffffu, t, off);
            if (lane + off < 32) t += t2;
        }
        wsuf[lane] = t;
    }
    __syncthreads();
    int suffix = v + ((warp < 31) ? wsuf[warp + 1] : 0);   // inclusive
    int above = suffix - gv;                               // suffix(t+1)
    if (suffix >= KTOP && above < KTOP) {
        int c = above;
        int bstar = 4 * tid;
        for (int b = 4 * tid + 3; b >= 4 * tid; --b) {
            c += hist[b];
            if (c >= KTOP) { bstar = b; break; }
        }
        *s_bstar = bstar;
    }
    __syncthreads();
    return *s_bstar;
}

// bitonic sort ascending over 1024 smem keys; shuffle stages for j<=16.
__device__ __forceinline__ void bitonic1024(unsigned long long* keys, int tid) {
    {
        unsigned long long kv = keys[tid];
        #pragma unroll
        for (unsigned kk = 2; kk <= 32; kk <<= 1) {
            bool up = ((tid & kk) == 0);
            #pragma unroll
            for (unsigned j = kk >> 1; j >= 1; j >>= 1) {
                unsigned long long pv = __shfl_xor_sync(0xffffffffu, kv, j);
                bool keepmin = (((tid & j) == 0) == up);
                kv = keepmin ? uomin(kv, pv) : uomax(kv, pv);
            }
        }
        keys[tid] = kv;
    }
    __syncthreads();
    for (unsigned kk = 64; kk <= SURV; kk <<= 1) {
        bool up = ((tid & kk) == 0);
        for (unsigned j = kk >> 1; j >= 32; j >>= 1) {
            unsigned ixj = tid ^ j;
            if (ixj > tid) {
                unsigned long long a = keys[tid], b = keys[ixj];
                if ((a > b) == up) { keys[tid] = b; keys[ixj] = a; }
            }
            __syncthreads();
        }
        unsigned long long kv = keys[tid];
        #pragma unroll
        for (unsigned j = 16; j >= 1; j >>= 1) {
            unsigned long long pv = __shfl_xor_sync(0xffffffffu, kv, j);
            bool keepmin = (((tid & j) == 0) == up);
            kv = keepmin ? uomin(kv, pv) : uomax(kv, pv);
        }
        keys[tid] = kv;
        __syncthreads();
    }
}

// ---------------------------------------------------------------------------
// 3x3 NMS on PRED heatmaps (reference NMS-es pred_hm only). One block per
// (image, 16-row chunk); each thread handles 2 consecutive rows of 1 column:
// vertical window loads carried in registers (2 new smem loads / 2 px),
// horizontal max via warp shuffles (smem only at warp edges).
// Survivor key (~fbits<<32)|idx => asc sort == lax.top_k order.
__global__ void __launch_bounds__(WID) k_nms(const float* __restrict__ pred_hm) {
    __shared__ float stage[STAGE_ROWS][WID];              // 18 KB
    __shared__ unsigned long long cbuf[STAGE_MAX];        // 8 KB
    __shared__ int s_cnt, s_base;

    int img   = blockIdx.x >> 4;            // / NCHUNK
    int chunk = blockIdx.x & (NCHUNK - 1);
    int y0 = chunk * RCHUNK;
    const float* hm = pred_hm + (size_t)img * HW;
    int x = threadIdx.x;
    int lane = x & 31;

    #pragma unroll
    for (int r = 0; r < STAGE_ROWS; r++) {
        int y = y0 - 1 + r;
        stage[r][x] = (y >= 0 && y < WID) ? __ldg(&hm[y * WID + x]) : -1.0f;
    }
    if (x == 0) s_cnt = 0;
    __syncthreads();

    auto append = [&](bool ok, float v, int y) {
        unsigned ballot = __ballot_sync(0xffffffffu, ok);
        if (ok) {
            int leader = __ffs(ballot) - 1;
            int base = 0;
            if (lane == leader) base = atomicAdd(&s_cnt, __popc(ballot));
            base = __shfl_sync(ballot, base, leader);
            int slot = base + __popc(ballot & ((1u << lane) - 1u));
            if (slot < STAGE_MAX) {
                unsigned fb = __float_as_uint(v);
                cbuf[slot] = ((unsigned long long)(~fb) << 32)
                           | (unsigned)(y * WID + x);
            }
        }
    };

    float s0 = stage[0][x], s1 = stage[1][x], s2 = stage[2][x], s3 = stage[3][x];
    #pragma unroll
    for (int pr = 0; pr < RCHUNK / 2; pr++) {
        float vm0 = max3f(s0, s1, s2);     // vertical max for row y0+2pr
        float vm1 = max3f(s1, s2, s3);     // for row y0+2pr+1
        float l0 = __shfl_up_sync(0xffffffffu, vm0, 1);
        float l1 = __shfl_up_sync(0xffffffffu, vm1, 1);
        float r0 = __shfl_down_sync(0xffffffffu, vm0, 1);
        float r1 = __shfl_down_sync(0xffffffffu, vm1, 1);
        if (lane == 0) {
            if (x == 0) { l0 = -1.0f; l1 = -1.0f; }
            else {
                int xm = x - 1;
                l0 = max3f(stage[2*pr][xm], stage[2*pr+1][xm], stage[2*pr+2][xm]);
                l1 = max3f(stage[2*pr+1][xm], stage[2*pr+2][xm], stage[2*pr+3][xm]);
            }
        }
        if (lane == 31) {
            if (x == WID - 1) { r0 = -1.0f; r1 = -1.0f; }
            else {
                int xp = x + 1;
                r0 = max3f(stage[2*pr][xp], stage[2*pr+1][xp], stage[2*pr+2][xp]);
                r1 = max3f(stage[2*pr+1][xp], stage[2*pr+2][xp], stage[2*pr+3][xp]);
            }
        }
        float v0 = s1, v1 = s2;
        // window max includes center => exactly hmax==heat semantics
        bool ok0 = (v0 > 0.0f) && (v0 >= vm0) && (v0 >= l0) && (v0 >= r0);
        bool ok1 = (v1 > 0.0f) && (v1 >= vm1) && (v1 >= l1) && (v1 >= r1);
        append(ok0, v0, y0 + 2*pr);
        append(ok1, v1, y0 + 2*pr + 1);
        if (pr < RCHUNK / 2 - 1) {
            s0 = s2; s1 = s3;
            s2 = stage[2*pr + 4][x];
            s3 = stage[2*pr + 5][x];
        }
    }
    __syncthreads();

    int cnt = s_cnt; if (cnt > STAGE_MAX) cnt = STAGE_MAX;
    if (x == 0) s_base = atomicAdd(&g_cnt[img], cnt);
    __syncthreads();
    int base = s_base;
    for (int i = x; i < cnt; i += WID) {
        int slot = base + i;
        if (slot < CAND_MAX) g_cand[img][slot] = cbuf[i];
    }
}

// ---------------------------------------------------------------------------
// PRED exact ordered top-500 (one CTA per image, over NMS survivors).
__global__ void __launch_bounds__(1024) k_select_pred() {
    __shared__ int hist[BINS];                  // 16 KB
    __shared__ unsigned long long keys[SURV];   // 8 KB
    __shared__ int wsuf[32];
    __shared__ int s_bstar, s_nsurv;

    int img = blockIdx.x;
    int tid = threadIdx.x;
    int lane = tid & 31;
    int n = g_cnt[img]; if (n > CAND_MAX) n = CAND_MAX;

    for (int i = tid; i < BINS; i += 1024) hist[i] = 0;
    if (tid == 0) { s_bstar = 0; s_nsurv = 0; }
    __syncthreads();

    for (int i = tid; i < n; i += 1024) {
        float v = __uint_as_float(~(unsigned)(g_cand[img][i] >> 32));
        atomicAdd(&hist[val_bin(v)], 1);
    }
    __syncthreads();

    int bstar = compute_bstar(hist, wsuf, &s_bstar, tid);

    int n_pad = (n + 1023) & ~1023;
    for (int i = tid; i < n_pad; i += 1024) {
        unsigned long long key = 0; bool pass = false;
        if (i < n) {
            key = g_cand[img][i];
            float vv = __uint_as_float(~(unsigned)(key >> 32));
            pass = (val_bin(vv) >= bstar);
        }
        unsigned ballot = __ballot_sync(0xffffffffu, pass);
        if (pass) {
            int leader = __ffs(ballot) - 1;
            int base = 0;
            if (lane == leader) base = atomicAdd(&s_nsurv, __popc(ballot));
            base = __shfl_sync(ballot, base, leader);
            int slot = base + __popc(ballot & ((1u << lane) - 1u));
            if (slot < SURV) keys[slot] = key;
        }
    }
    __syncthreads();
    int ns = s_nsurv; if (ns > SURV) ns = SURV;
    if (tid >= ns) keys[tid] = 0xFFFFFFFFFFFFFFFFULL;
    __syncthreads();

    bitonic1024(keys, tid);

    if (tid < KTOP) {
        unsigned p = (unsigned)(keys[tid] & 0xFFFFFFFFULL);
        g_xs[img][tid] = (float)(p & (WID - 1));
        g_ys[img][tid] = (float)(p >> 8);
    }
    if (tid == 0) g_cnt[img] = 0;   // reset for next graph replay
}

// ---------------------------------------------------------------------------
// GT top-500: SINGLE pass (reference applies top_k to raw gt_hm — no NMS).
// While histogramming every pixel, prefilter v >= 0.98 into a smem buffer
// (E~1311 <= 1536 at 6 sigma). Exact bstar from the full histogram; guard
// bstar >= SAFE_BIN ensures the buffer contains every survivor (bin 4015
// starts above 0.98). Fallback second pass if the guard ever fails.
__global__ void __launch_bounds__(1024) k_gt(const float* __restrict__ gt_hm) {
    __shared__ int hist[BINS];                       // 16 KB
    __shared__ unsigned long long pre[PRE_MAX];      // 12 KB
    __shared__ unsigned long long keys[SURV];        // 8 KB
    __shared__ int wsuf[32];
    __shared__ int s_bstar, s_pre, s_nsurv;

    int img = blockIdx.x;
    int tid = threadIdx.x;
    int lane = tid & 31;
    const float4* hm4 = reinterpret_cast<const float4*>(gt_hm + (size_t)img * HW);

    for (int i = tid; i < BINS; i += 1024) hist[i] = 0;
    if (tid == 0) { s_bstar = 0; s_pre = 0; s_nsurv = 0; }
    __syncthreads();

    // single pass: histogram all + prefilter
    #pragma unroll 2
    for (int i = tid; i < HW / 4; i += 1024) {
        float4 v4 = __ldg(&hm4[i]);
        float vv[4] = {v4.x, v4.y, v4.z, v4.w};
        #pragma unroll
        for (int comp = 0; comp < 4; comp++) {
            atomicAdd(&hist[val_bin(vv[comp])], 1);
            bool keep = (vv[comp] >= PRE_THRESH);
            unsigned ballot = __ballot_sync(0xffffffffu, keep);
            if (keep) {
                int leader = __ffs(ballot) - 1;
                int base = 0;
                if (lane == leader) base = atomicAdd(&s_pre, __popc(ballot));
                base = __shfl_sync(ballot, base, leader);
                int slot = base + __popc(ballot & ((1u << lane) - 1u));
                if (slot < PRE_MAX) {
                    unsigned fb = __float_as_uint(vv[comp]);
                    pre[slot] = ((unsigned long long)(~fb) << 32)
                              | (unsigned)(4 * i + comp);
                }
            }
        }
    }
    __syncthreads();

    int bstar = compute_bstar(hist, wsuf, &s_bstar, tid);
    int npre = s_pre;
    bool ok_fast = (bstar >= SAFE_BIN) && (npre <= PRE_MAX);

    if (ok_fast) {
        int n_pad = (npre + 1023) & ~1023;
        for (int i = tid; i < n_pad; i += 1024) {
            unsigned long long key = 0; bool pass = false;
            if (i < npre) {
                key = pre[i];
                float vv = __uint_as_float(~(unsigned)(key >> 32));
                pass = (val_bin(vv) >= bstar);
            }
            unsigned ballot = __ballot_sync(0xffffffffu, pass);
            if (pass) {
                int leader = __ffs(ballot) - 1;
                int base = 0;
                if (lane == leader) base = atomicAdd(&s_nsurv, __popc(ballot));
                base = __shfl_sync(ballot, base, leader);
                int slot = base + __popc(ballot & ((1u << lane) - 1u));
                if (slot < SURV) keys[slot] = key;
            }
        }
    } else {
        // fallback: re-stream and collect everything >= bstar (never in practice)
        #pragma unroll 2
        for (int i = tid; i < HW / 4; i += 1024) {
            float4 v4 = __ldg(&hm4[i]);
            float vv[4] = {v4.x, v4.y, v4.z, v4.w};
            #pragma unroll
            for (int comp = 0; comp < 4; comp++) {
                bool pass = (val_bin(vv[comp]) >= bstar);
                unsigned ballot = __ballot_sync(0xffffffffu, pass);
                if (pass) {
                    int leader = __ffs(ballot) - 1;
                    int base = 0;
                    if (lane == leader) base = atomicAdd(&s_nsurv, __popc(ballot));
                    base = __shfl_sync(ballot, base, leader);
                    int slot = base + __popc(ballot & ((1u << lane) - 1u));
                    if (slot < SURV) {
                        unsigned fb = __float_as_uint(vv[comp]);
                        keys[slot] = ((unsigned long long)(~fb) << 32)
                                   | (unsigned)(4 * i + comp);
                    }
                }
            }
        }
    }
    __syncthreads();
    int ns = s_nsurv; if (ns > SURV) ns = SURV;
    if (tid >= ns) keys[tid] = 0xFFFFFFFFFFFFFFFFULL;
    __syncthreads();

    bitonic1024(keys, tid);

    if (tid < KTOP) {
        unsigned p = (unsigned)(keys[tid] & 0xFFFFFFFFULL);
        g_xs[NB + img][tid] = (float)(p & (WID - 1));
        g_ys[NB + img][tid] = (float)(p >> 8);
    }
}

// ---------------------------------------------------------------------------
// Loss: one thread per (item, coordinate, side) — 320K threads. Side 0 = pred
// (scattered gathers), side 1 = gt (coalesced); paired via shfl_xor(1).
#define LOSS_TPB 1024
#define LOSS_N2  (NB * KTOP * 20)
__global__ void __launch_bounds__(LOSS_TPB)
k_loss(const float* __restrict__ pred_wh, const float* __restrict__ pred_reg,
       const float* __restrict__ pred_cls,
       const float* __restrict__ gt_wh, const float* __restrict__ gt_reg,
       const float* __restrict__ gt_cls,
       const int* __restrict__ gt_ind, const int* __restrict__ gt_mask,
       float* __restrict__ out) {
    int gidx = blockIdx.x * LOSS_TPB + threadIdx.x;
    float val = 0.f;
    int mask = 0;
    bool gtside = gidx & 1;
    if (gidx < LOSS_N2) {
        int t = gidx / 20;
        int rem = gidx - t * 20;
        int c = rem >> 1;
        mask = __ldg(&gt_mask[t]);
        if (mask) {
            int b = t / KTOP, k = t - b * KTOP;
            bool odd = c & 1;
            int iA = c_whA[c], iB = c_whB[c];
            float sg = c_sgn[c];
            if (gtside) {
                float base = odd ? (g_ys[NB + b][k] + __ldg(&gt_reg[2 * t + 1]))
                                 : (g_xs[NB + b][k] + __ldg(&gt_reg[2 * t]));
                bool gm = __ldg(&gt_cls[t]) > 0.8f;
                val = base;
                if (gm) { if (iA >= 0) val += __ldg(&gt_wh[10 * t + iA]); }
                else    { if (iB >= 0) val += sg * __ldg(&gt_wh[10 * t + iB]); }
            } else {
                int ind = __ldg(&gt_ind[t]);
                float base = odd ? (g_ys[b][k] + __ldg(&pred_reg[(size_t)(b * 2 + 1) * HW + ind]))
                                 : (g_xs[b][k] + __ldg(&pred_reg[(size_t)(b * 2) * HW + ind]));
                bool m = __ldg(&pred_cls[(size_t)b * HW + ind]) > 0.8f;
                val = base;
                if (m) { if (iA >= 0) val += __ldg(&pred_wh[((size_t)b * 10 + iA) * HW + ind]); }
                else   { if (iB >= 0) val += sg * __ldg(&pred_wh[((size_t)b * 10 + iB) * HW + ind]); }
            }
        }
    }
    float other = __shfl_xor_sync(0xffffffffu, val, 1);
    float lsum = 0.f;
    int lcnt = 0;
    if (gidx < LOSS_N2 && !gtside && mask) {
        float d = fabsf(val - other);
        lsum = (d < 1.f) ? 0.5f * d * d : (d - 0.5f);
        lcnt = 1;
    }
    #pragma unroll
    for (int off = 16; off > 0; off >>= 1) {
        lsum += __shfl_down_sync(0xffffffffu, lsum, off);
        lcnt += __shfl_down_sync(0xffffffffu, lcnt, off);
    }
    __shared__ float wsum[LOSS_TPB / 32];
    __shared__ int   wcnt[LOSS_TPB / 32];
    int warp = threadIdx.x >> 5, lane = threadIdx.x & 31;
    if (lane == 0) { wsum[warp] = lsum; wcnt[warp] = lcnt; }
    __syncthreads();
    if (warp == 0) {
        float s = (lane < LOSS_TPB / 32) ? wsum[lane] : 0.f;
        int   cc = (lane < LOSS_TPB / 32) ? wcnt[lane] : 0;
        #pragma unroll
        for (int off = 16; off > 0; off >>= 1) {
            s  += __shfl_down_sync(0xffffffffu, s, off);
            cc += __shfl_down_sync(0xffffffffu, cc, off);
        }
        if (lane == 0) {
            atomicAdd(&g_sum, (double)s);
            atomicAdd(&g_tot, cc);
            __threadfence();
            unsigned ticket = atomicAdd(&g_ticket, 1u);
            if (ticket == gridDim.x - 1) {
                double fs = g_sum;
                int tot = g_tot;
                float loss = 0.f;
                if (tot > 0) loss = (float)(fs / (double)(tot < 1 ? 1 : tot));
                out[0] = loss;
                g_sum = 0.0; g_tot = 0; g_ticket = 0u;
            }
        }
    }
}

// ---------------------------------------------------------------------------
extern "C" void kernel_launch(void* const* d_in, const int* in_sizes, int n_in,
                              void* d_out, int out_size) {
    const float* pred_hm  = (const float*)d_in[0];
    const float* pred_wh  = (const float*)d_in[1];
    const float* pred_reg = (const float*)d_in[2];
    const float* pred_cls = (const float*)d_in[3];
    const float* gt_hm    = (const float*)d_in[4];
    const float* gt_wh    = (const float*)d_in[5];
    const float* gt_reg   = (const float*)d_in[6];
    const float* gt_cls   = (const float*)d_in[7];
    const int*   gt_ind   = (const int*)d_in[8];
    const int*   gt_mask  = (const int*)d_in[9];
    float* out = (float*)d_out;

    static cudaStream_t s2 = nullptr;
    static cudaEvent_t evFork = nullptr, evJoin = nullptr;
    if (s2 == nullptr) {
        cudaStreamCreateWithFlags(&s2, cudaStreamNonBlocking);
        cudaEventCreateWithFlags(&evFork, cudaEventDisableTiming);
        cudaEventCreateWithFlags(&evJoin, cudaEventDisableTiming);
    }

    cudaEventRecord(evFork, 0);
    cudaStreamWaitEvent(s2, evFork, 0);
    k_gt<<<NB, 1024, 0, s2>>>(gt_hm);                 // gt branch (single pass)
    cudaEventRecord(evJoin, s2);

    k_nms<<<NB * NCHUNK, WID>>>(pred_hm);             // pred branch
    k_select_pred<<<NB, 1024>>>();

    cudaStreamWaitEvent(0, evJoin, 0);
    k_loss<<<(LOSS_N2 + LOSS_TPB - 1) / LOSS_TPB, LOSS_TPB>>>(
        pred_wh, pred_reg, pred_cls, gt_wh, gt_reg, gt_cls, gt_ind, gt_mask, out);
}